// round 2
// baseline (speedup 1.0000x reference)
#include <cuda_runtime.h>
#include <cuda_bf16.h>
#include <cstdint>

#define DI __device__ __forceinline__

// ---------------------------------------------------------------------------
// Problem:
//   x   : (N=32, C=128, T=512, F=32) fp32
//   out : (N, C, C, F) fp32
//   out[n,i,j,f] = exp(-||x[n,i,:,f]-x[n,j,:,f]||^2 / (2 sigma^2))
// Scratch: x transposed to (N, F, C, T) bf16  -> 128 MiB device global
// NOTE: harness compiles via compute_103 (no 'a') => tcgen05 unavailable.
//       Use mma.sync (HMMA) bf16 path instead.
// ---------------------------------------------------------------------------
#define NB 32
#define CC 128
#define TT 512
#define FF 32

__device__ __nv_bfloat16 g_xb[(size_t)NB * FF * CC * TT];

// ---------------------------------------------------------------------------
// Kernel 1: (N,C,T,F) fp32 -> (N,F,C,T) bf16   (coalesced tile transpose)
// grid (T/32, C, N), block (32, 8)
// ---------------------------------------------------------------------------
__global__ void k_transpose(const float* __restrict__ x) {
    __shared__ float tile[32][33];
    const int t0 = blockIdx.x * 32;
    const int c  = blockIdx.y;
    const int n  = blockIdx.z;

    const float* src = x + (((size_t)(n * CC + c)) * TT + t0) * FF;
#pragma unroll
    for (int r = 0; r < 4; r++) {
        int t = threadIdx.y + r * 8;
        tile[t][threadIdx.x] = src[(size_t)t * FF + threadIdx.x];
    }
    __syncthreads();

    __nv_bfloat16* dst = g_xb + ((size_t)(n * FF) * CC + c) * TT + t0;
#pragma unroll
    for (int r = 0; r < 4; r++) {
        int fi = threadIdx.y + r * 8;
        dst[(size_t)fi * CC * TT + threadIdx.x] =
            __float2bfloat16(tile[threadIdx.x][fi]);
    }
}

// ---------------------------------------------------------------------------
// Kernel 2: per-(n,f) 128x128 gram via mma.sync bf16 + fused dist/exp epilogue
//
// grid = N*F = 1024 CTAs, block = 256 (8 warps, 2x4 -> warp tile m64 n32)
// K loop: 512 in 8 chunks of 64, double-buffered cp.async.
// SMEM chunk tile: [128 rows][72 cols] bf16 (row stride 144 B) -> fragment
// lds.b32 bank = (36*row + c) mod 32, all 32 lanes distinct (conflict-free).
// ---------------------------------------------------------------------------
#define CHUNK      64
#define NCHUNK     8
#define ROW_ELEMS  72            // 64 data + 8 pad
#define ROW_BYTES  144
#define STAGE_B    (128 * ROW_BYTES)        // 18432
#define SDIAG_OFF  (2 * STAGE_B)            // 36864
#define SMEM_SZ    (SDIAG_OFF + 128 * 4)    // 37376

DI void cp16(void* saddr, const void* g) {
    uint32_t a;
    asm("{ .reg .u64 t; cvta.to.shared.u64 t, %1; cvt.u32.u64 %0, t; }"
        : "=r"(a) : "l"(saddr));
    asm volatile("cp.async.cg.shared.global [%0], [%1], 16;"
                 :: "r"(a), "l"(g) : "memory");
}
DI void cp_commit() { asm volatile("cp.async.commit_group;" ::: "memory"); }
DI void cp_wait_1() { asm volatile("cp.async.wait_group 1;" ::: "memory"); }
DI void cp_wait_0() { asm volatile("cp.async.wait_group 0;" ::: "memory"); }

DI void mma16816(float& c0, float& c1, float& c2, float& c3,
                 uint32_t a0, uint32_t a1, uint32_t a2, uint32_t a3,
                 uint32_t b0, uint32_t b1) {
    asm volatile(
        "mma.sync.aligned.m16n8k16.row.col.f32.bf16.bf16.f32 "
        "{%0,%1,%2,%3}, {%4,%5,%6,%7}, {%8,%9}, {%0,%1,%2,%3};"
        : "+f"(c0), "+f"(c1), "+f"(c2), "+f"(c3)
        : "r"(a0), "r"(a1), "r"(a2), "r"(a3), "r"(b0), "r"(b1));
}

// load one chunk: rows 0..127 of A (bf16, row stride TT) cols [k0, k0+64)
DI void load_chunk(const __nv_bfloat16* A, char* buf, int tid, int k0) {
    const int row  = tid >> 1;          // 2 threads per row
    const int half = tid & 1;
    const __nv_bfloat16* g = A + (size_t)row * TT + k0 + half * 32;
    char* s = buf + row * ROW_BYTES + half * 64;
#pragma unroll
    for (int v = 0; v < 4; v++)
        cp16(s + v * 16, g + v * 8);
}

extern "C" __global__ void __launch_bounds__(256, 2)
k_gram(const float* __restrict__ sigma, float* __restrict__ out) {
    extern __shared__ char smem[];
    const int tid  = threadIdx.x;
    const int wid  = tid >> 5;
    const int lane = tid & 31;
    const int g    = lane >> 2;         // group id 0..7
    const int c4   = lane & 3;          // 0..3
    const int bid  = blockIdx.x;
    const int n    = bid >> 5;
    const int f    = bid & 31;

    const int RM = (wid >> 2) * 64;     // warp row base
    const int CN = (wid & 3) * 32;      // warp col base

    const __nv_bfloat16* A = g_xb + (size_t)bid * CC * TT;

    float acc[4][4][4];
#pragma unroll
    for (int mt = 0; mt < 4; mt++)
#pragma unroll
        for (int nt = 0; nt < 4; nt++)
#pragma unroll
            for (int r = 0; r < 4; r++) acc[mt][nt][r] = 0.f;

    // ---- pipelined main loop ----
    load_chunk(A, smem, tid, 0);
    cp_commit();

#pragma unroll 1
    for (int k = 0; k < NCHUNK; k++) {
        char* buf = smem + (k & 1) * STAGE_B;
        if (k + 1 < NCHUNK) {
            load_chunk(A, smem + ((k + 1) & 1) * STAGE_B, tid, (k + 1) * CHUNK);
            cp_commit();
            cp_wait_1();
        } else {
            cp_wait_0();
        }
        __syncthreads();

#pragma unroll
        for (int ks = 0; ks < 4; ks++) {
            const int kb = ks * 16 + c4 * 2;    // elem col of this thread's pair
            // A fragments: rows RM + mt*16 + {g, g+8}, cols kb, kb+8
            uint32_t af[4][4];
#pragma unroll
            for (int mt = 0; mt < 4; mt++) {
                const char* r0 = buf + (RM + mt * 16 + g) * ROW_BYTES;
                af[mt][0] = *(const uint32_t*)(r0 + kb * 2);
                af[mt][1] = *(const uint32_t*)(r0 + 8 * ROW_BYTES + kb * 2);
                af[mt][2] = *(const uint32_t*)(r0 + (kb + 8) * 2);
                af[mt][3] = *(const uint32_t*)(r0 + 8 * ROW_BYTES + (kb + 8) * 2);
            }
            // B fragments: row (=n) CN + nt*8 + g, cols kb, kb+8
            uint32_t bf[4][2];
#pragma unroll
            for (int nt = 0; nt < 4; nt++) {
                const char* r0 = buf + (CN + nt * 8 + g) * ROW_BYTES;
                bf[nt][0] = *(const uint32_t*)(r0 + kb * 2);
                bf[nt][1] = *(const uint32_t*)(r0 + (kb + 8) * 2);
            }
#pragma unroll
            for (int mt = 0; mt < 4; mt++)
#pragma unroll
                for (int nt = 0; nt < 4; nt++)
                    mma16816(acc[mt][nt][0], acc[mt][nt][1],
                             acc[mt][nt][2], acc[mt][nt][3],
                             af[mt][0], af[mt][1], af[mt][2], af[mt][3],
                             bf[nt][0], bf[nt][1]);
        }
        __syncthreads();
    }

    // ---- epilogue ----
    float* sdiag = reinterpret_cast<float*>(smem + SDIAG_OFF);

    // extract diagonal from accumulators (exact cancellation on the diagonal)
#pragma unroll
    for (int mt = 0; mt < 4; mt++)
#pragma unroll
        for (int nt = 0; nt < 4; nt++)
#pragma unroll
            for (int r = 0; r < 4; r++) {
                const int i = RM + mt * 16 + g + ((r >> 1) << 3);
                const int j = CN + nt * 8 + c4 * 2 + (r & 1);
                if (i == j) sdiag[i] = acc[mt][nt][r];
            }
    __syncthreads();

    const float sg   = sigma[0];
    const float ninv = -0.5f / (sg * sg);

    float* on = out + (size_t)n * CC * CC * FF + f;
#pragma unroll
    for (int mt = 0; mt < 4; mt++) {
#pragma unroll
        for (int rh = 0; rh < 2; rh++) {
            const int i  = RM + mt * 16 + g + rh * 8;
            const float di = sdiag[i];
            float* orow = on + (size_t)i * CC * FF;
#pragma unroll
            for (int nt = 0; nt < 4; nt++) {
                const int j0 = CN + nt * 8 + c4 * 2;
                const float g0 = acc[mt][nt][rh * 2 + 0];
                const float g1 = acc[mt][nt][rh * 2 + 1];
                const float d20 = fmaxf(di + sdiag[j0]     - 2.0f * g0, 0.0f);
                const float d21 = fmaxf(di + sdiag[j0 + 1] - 2.0f * g1, 0.0f);
                orow[(size_t)j0 * FF]       = __expf(d20 * ninv);
                orow[(size_t)(j0 + 1) * FF] = __expf(d21 * ninv);
            }
        }
    }
}

// ---------------------------------------------------------------------------
// launch
// ---------------------------------------------------------------------------
extern "C" void kernel_launch(void* const* d_in, const int* in_sizes, int n_in,
                              void* d_out, int out_size) {
    const float* x     = (const float*)d_in[0];
    const float* sigma = (const float*)d_in[1];
    float* out         = (float*)d_out;
    (void)in_sizes; (void)n_in; (void)out_size;

    dim3 g1(TT / 32, CC, NB), b1(32, 8);
    k_transpose<<<g1, b1>>>(x);

    cudaFuncSetAttribute(k_gram, cudaFuncAttributeMaxDynamicSharedMemorySize, SMEM_SZ);
    k_gram<<<NB * FF, 256, SMEM_SZ>>>(sigma, out);
}